// round 8
// baseline (speedup 1.0000x reference)
#include <cuda_runtime.h>
#include <cuda_fp16.h>
#include <cstdint>

// Problem constants
#define BATCH 4
#define HH 1080
#define WW 1920
#define NLUT 33
#define HW (HH * WW)                 // 2,073,600
#define PAIRS_PER (NLUT * NLUT * 32) // 34,848 half2 entries per (b,c)
#define NCOMBO 12                    // 4 batches * 3 channels
#define TOTAL_PAIRS (NCOMBO * PAIRS_PER)
#define SMEM_BYTES (PAIRS_PER * 4)   // 139,392 B
#define SUBS 12                      // CTAs per combo
#define TPB 1024

// Scratch: x-pair-expanded fp16 LUT, per (batch,channel).
// entry[((bc*33 + z)*33 + y)*32 + x0] = (lut[z][y][x0], lut[z][y][x0+1])
__device__ __half2 g_pairs[TOTAL_PAIRS];

__global__ void build_pairs_kernel(const float* __restrict__ lut) {
    int idx = blockIdx.x * blockDim.x + threadIdx.x;
    if (idx >= TOTAL_PAIRS) return;
    int x0 = idx & 31;
    int t = idx >> 5;
    int y = t % NLUT; t /= NLUT;
    int z = t % NLUT;
    int bc = t / NLUT;
    int s = bc * (NLUT * NLUT * NLUT) + (z * NLUT + y) * NLUT + x0;
    g_pairs[idx] = __floats2half2_rn(lut[s], lut[s + 1]);
}

__device__ __forceinline__ void cp_async16(unsigned int smem_addr, const void* gptr) {
    asm volatile("cp.async.cg.shared.global [%0], [%1], 16;\n"
                 :: "r"(smem_addr), "l"(gptr) : "memory");
}

__global__ void __launch_bounds__(TPB, 1)
lut_apply_kernel(const float* __restrict__ img, float* __restrict__ out) {
    extern __shared__ __half2 s_pairs[];
    const int combo = blockIdx.x % NCOMBO; // interleave: same-batch CTAs co-run (L2 reuse)
    const int sub = blockIdx.x / NCOMBO;   // 0..SUBS-1
    const int b = combo / 3;
    const int c = combo % 3;

    const float4* cx = reinterpret_cast<const float4*>(img + (size_t)b * 3 * HW);
    const float4* cy = cx + HW / 4;
    const float4* cz = cy + HW / 4;
    float4* o4 = reinterpret_cast<float4*>(out + (size_t)(b * 3 + c) * HW);

    const int npix4 = HW / 4;     // 518,400
    const int stride = SUBS * TPB;

    // Stage this combo's pair table with cp.async (no register round-trip;
    // all 9 LDGSTS in flight before a single wait).
    {
        const uint4* src = reinterpret_cast<const uint4*>(g_pairs + combo * PAIRS_PER);
        unsigned int sbase;
        asm("{ .reg .u64 t; cvta.to.shared.u64 t, %1; cvt.u32.u64 %0, t; }"
            : "=r"(sbase) : "l"(s_pairs));
        const int n16 = PAIRS_PER / 4; // 8712
#pragma unroll
        for (int k = 0; k < 9; k++) {
            int i = threadIdx.x + k * TPB;
            if (i < n16) cp_async16(sbase + i * 16, src + i);
        }
        asm volatile("cp.async.commit_group;\n" ::: "memory");
    }

    // Iteration 0's image loads overlap the async staging.
    int p = sub * TPB + threadIdx.x;   // always < npix4
    float4 X = cx[p];
    float4 Y = cy[p];
    float4 Z = cz[p];

    asm volatile("cp.async.wait_group 0;\n" ::: "memory");
    __syncthreads();

    // Software-pipelined main loop. All 16 LDS of the 4 taps are issued as
    // one batch so their 29-cycle latency is exposed once per iteration,
    // not four times.
#pragma unroll 1
    for (; p < npix4; p += stride) {
        int pn = min(p + stride, npix4 - 1);  // branchless prefetch guard
        float4 Xn = cx[pn];
        float4 Yn = cy[pn];
        float4 Zn = cz[pn];

        float xs[4] = {X.x, X.y, X.z, X.w};
        float ys[4] = {Y.x, Y.y, Y.z, Y.w};
        float zs[4] = {Z.x, Z.y, Z.z, Z.w};

        float wx[4], wy[4], wz[4];
        int base[4];
#pragma unroll
        for (int j = 0; j < 4; j++) {
            // __saturatef + scale 31.999998 (vs exact 32): guarantees i0 <= 31
            // so +32/+1056/+1088 stay in-bounds; the 6e-8 coordinate
            // perturbation is ~1e-6 in the output (interp is continuous).
            float fx = __saturatef(xs[j]) * 31.999998f;
            float fy = __saturatef(ys[j]) * 31.999998f;
            float fz = __saturatef(zs[j]) * 31.999998f;
            int ix = (int)fx;
            int iy = (int)fy;
            int iz = (int)fz;
            wx[j] = fx - (float)ix;
            wy[j] = fy - (float)iy;
            wz[j] = fz - (float)iz;
            base[j] = (iz * NLUT + iy) * 32 + ix;
        }

        __half2 q00[4], q01[4], q10[4], q11[4];
#pragma unroll
        for (int j = 0; j < 4; j++) {
            q00[j] = s_pairs[base[j]];                  // (z0,y0): x0,x1 packed
            q01[j] = s_pairs[base[j] + 32];             // (z0,y1)
            q10[j] = s_pairs[base[j] + NLUT * 32];      // (z1,y0)
            q11[j] = s_pairs[base[j] + NLUT * 32 + 32]; // (z1,y1)
        }

        float r[4];
#pragma unroll
        for (int j = 0; j < 4; j++) {
            float2 a00 = __half22float2(q00[j]);
            float2 a01 = __half22float2(q01[j]);
            float2 a10 = __half22float2(q10[j]);
            float2 a11 = __half22float2(q11[j]);
            float c00 = fmaf(wx[j], a00.y - a00.x, a00.x);
            float c01 = fmaf(wx[j], a01.y - a01.x, a01.x);
            float c10 = fmaf(wx[j], a10.y - a10.x, a10.x);
            float c11 = fmaf(wx[j], a11.y - a11.x, a11.x);
            float c0 = fmaf(wy[j], c01 - c00, c00);
            float c1 = fmaf(wy[j], c11 - c10, c10);
            r[j] = fmaf(wz[j], c1 - c0, c0);
        }

        float4 R = {r[0], r[1], r[2], r[3]};
        o4[p] = R;

        X = Xn; Y = Yn; Z = Zn;
    }
}

extern "C" void kernel_launch(void* const* d_in, const int* in_sizes, int n_in,
                              void* d_out, int out_size) {
    const float* img = (const float*)d_in[0]; // (4,3,1080,1920) f32
    const float* lut = (const float*)d_in[1]; // (4,3,33,33,33) f32
    float* out = (float*)d_out;

    cudaFuncSetAttribute(lut_apply_kernel,
                         cudaFuncAttributeMaxDynamicSharedMemorySize, SMEM_BYTES);

    build_pairs_kernel<<<(TOTAL_PAIRS + 255) / 256, 256>>>(lut);
    lut_apply_kernel<<<NCOMBO * SUBS, TPB, SMEM_BYTES>>>(img, out);
}

// round 9
// speedup vs baseline: 1.5620x; 1.5620x over previous
#include <cuda_runtime.h>
#include <cuda_fp16.h>
#include <cstdint>

// Problem constants
#define BATCH 4
#define HH 1080
#define WW 1920
#define NLUT 33
#define HW (HH * WW)                 // 2,073,600
#define PAIRS_PER (NLUT * NLUT * 32) // 34,848 half2 entries per (b,c)
#define NCOMBO 12                    // 4 batches * 3 channels
#define TOTAL_PAIRS (NCOMBO * PAIRS_PER)
#define SMEM_BYTES (PAIRS_PER * 4)   // 139,392 B
#define SUBS 12                      // CTAs per combo
#define TPB 1024

// Scratch: x-pair-expanded fp16 LUT, per (batch,channel).
// entry[((bc*33 + z)*33 + y)*32 + x0] = (lut[z][y][x0], lut[z][y][x0+1])
__device__ __half2 g_pairs[TOTAL_PAIRS];

__global__ void build_pairs_kernel(const float* __restrict__ lut) {
    int idx = blockIdx.x * blockDim.x + threadIdx.x;
    if (idx >= TOTAL_PAIRS) return;
    int x0 = idx & 31;
    int t = idx >> 5;
    int y = t % NLUT; t /= NLUT;
    int z = t % NLUT;
    int bc = t / NLUT;
    int s = bc * (NLUT * NLUT * NLUT) + (z * NLUT + y) * NLUT + x0;
    g_pairs[idx] = __floats2half2_rn(lut[s], lut[s + 1]);
}

__device__ __forceinline__ void cp_async16(unsigned int smem_addr, const void* gptr) {
    asm volatile("cp.async.cg.shared.global [%0], [%1], 16;\n"
                 :: "r"(smem_addr), "l"(gptr) : "memory");
}

__device__ __forceinline__ float tap(const __half2* __restrict__ sp,
                                     float x, float y, float z) {
    // __saturatef clamps to [0,1]; scale by 31.999998 (vs exact 32) so
    // i0 <= 31 always, keeping the +32 / +1056 / +1088 offsets in-bounds.
    // Trilinear interp is continuous across cell boundaries, so the 6e-8
    // relative coordinate perturbation is ~1e-6 in the output — far below
    // the table's fp16 quantization (~1e-4).
    float fx = __saturatef(x) * 31.999998f;
    float fy = __saturatef(y) * 31.999998f;
    float fz = __saturatef(z) * 31.999998f;
    int ix = (int)fx;
    int iy = (int)fy;
    int iz = (int)fz;
    float wx = fx - (float)ix;
    float wy = fy - (float)iy;
    float wz = fz - (float)iz;

    int base = (iz * NLUT + iy) * 32 + ix;
    __half2 q00 = sp[base];                  // (z0,y0): x0,x1 packed
    __half2 q01 = sp[base + 32];             // (z0,y1)
    __half2 q10 = sp[base + NLUT * 32];      // (z1,y0)
    __half2 q11 = sp[base + NLUT * 32 + 32]; // (z1,y1)

    float2 a00 = __half22float2(q00);
    float2 a01 = __half22float2(q01);
    float2 a10 = __half22float2(q10);
    float2 a11 = __half22float2(q11);

    float c00 = fmaf(wx, a00.y - a00.x, a00.x);
    float c01 = fmaf(wx, a01.y - a01.x, a01.x);
    float c10 = fmaf(wx, a10.y - a10.x, a10.x);
    float c11 = fmaf(wx, a11.y - a11.x, a11.x);
    float c0 = fmaf(wy, c01 - c00, c00);
    float c1 = fmaf(wy, c11 - c10, c10);
    return fmaf(wz, c1 - c0, c0);
}

__global__ void __launch_bounds__(TPB, 1)
lut_apply_kernel(const float* __restrict__ img, float* __restrict__ out) {
    extern __shared__ __half2 s_pairs[];
    const int combo = blockIdx.x % NCOMBO; // interleave: same-batch CTAs co-run (L2 reuse)
    const int sub = blockIdx.x / NCOMBO;   // 0..SUBS-1
    const int b = combo / 3;
    const int c = combo % 3;

    const float4* cx = reinterpret_cast<const float4*>(img + (size_t)b * 3 * HW);
    const float4* cy = cx + HW / 4;
    const float4* cz = cy + HW / 4;
    float4* o4 = reinterpret_cast<float4*>(out + (size_t)(b * 3 + c) * HW);

    const int npix4 = HW / 4;     // 518,400
    const int stride = SUBS * TPB;

    // Stage this combo's pair table with cp.async: no register round-trip,
    // all 9 LDGSTS in flight before a single wait, and no registers consumed
    // that the main loop needs.
    {
        const uint4* src = reinterpret_cast<const uint4*>(g_pairs + combo * PAIRS_PER);
        unsigned int sbase;
        asm("{ .reg .u64 t; cvta.to.shared.u64 t, %1; cvt.u32.u64 %0, t; }"
            : "=r"(sbase) : "l"(s_pairs));
        const int n16 = PAIRS_PER / 4; // 8712
#pragma unroll
        for (int k = 0; k < 9; k++) {
            int i = threadIdx.x + k * TPB;
            if (i < n16) cp_async16(sbase + i * 16, src + i);
        }
        asm volatile("cp.async.commit_group;\n" ::: "memory");
    }

    // Iteration 0's image loads overlap the async staging.
    int p = sub * TPB + threadIdx.x;   // always < npix4
    float4 X = cx[p];
    float4 Y = cy[p];
    float4 Z = cz[p];

    asm volatile("cp.async.wait_group 0;\n" ::: "memory");
    __syncthreads();

    // Software-pipelined main loop: next iteration's global loads issue
    // before this iteration's (LDS-heavy) tap work consumes the current data.
    // Taps stay in function form — ptxas's tap-by-tap schedule is the
    // register-optimal one at 1024 threads (R6/R8 showed wider live ranges
    // spill or thrash the 64-reg cap).
#pragma unroll 1
    for (; p < npix4; p += stride) {
        int pn = min(p + stride, npix4 - 1);  // branchless prefetch guard
        float4 Xn = cx[pn];
        float4 Yn = cy[pn];
        float4 Zn = cz[pn];

        float4 R;
        R.x = tap(s_pairs, X.x, Y.x, Z.x);
        R.y = tap(s_pairs, X.y, Y.y, Z.y);
        R.z = tap(s_pairs, X.z, Y.z, Z.z);
        R.w = tap(s_pairs, X.w, Y.w, Z.w);
        o4[p] = R;

        X = Xn; Y = Yn; Z = Zn;
    }
}

extern "C" void kernel_launch(void* const* d_in, const int* in_sizes, int n_in,
                              void* d_out, int out_size) {
    const float* img = (const float*)d_in[0]; // (4,3,1080,1920) f32
    const float* lut = (const float*)d_in[1]; // (4,3,33,33,33) f32
    float* out = (float*)d_out;

    cudaFuncSetAttribute(lut_apply_kernel,
                         cudaFuncAttributeMaxDynamicSharedMemorySize, SMEM_BYTES);

    build_pairs_kernel<<<(TOTAL_PAIRS + 255) / 256, 256>>>(lut);
    lut_apply_kernel<<<NCOMBO * SUBS, TPB, SMEM_BYTES>>>(img, out);
}